// round 15
// baseline (speedup 1.0000x reference)
#include <cuda_runtime.h>
#include <cuda_fp16.h>
#include <cstdint>

// Rotated ROI cropper v14: v12 + XOR bank-swizzled texel tile.
//   x:     [8, 3, 1024, 1024] fp32
//   boxes: [8, 64, 5] fp32  (cx, cy, w, h, angle_deg)
//   out:   [512, 3, 48, 320] fp32
//
// Block = one 32x16 output tile (256 thr, 2 rows/thread).
// Texel = uint2 {half2(c0,c1), half2(c2,0)} = 8B = one bank-pair.
// Tile pitch 48 texels (384B, ==0 mod 16 bank-pairs) so bank-pair =
// swizzled-x mod 16. Swizzle: sx_col = lx ^ ((ly&3)<<2), applied in both
// staging stores (4-aligned mask keeps STS.128 contiguous) and taps
// (each tap is an independent LDS.64). Kills the diagonal-stride 4-way
// conflicts of the rotated access pattern.

#define IMG_H 1024
#define IMG_W 1024
#define OUT_H 48
#define OUT_W 320
#define CHANS 3
#define N_BOXES_TOTAL 512
#define PLANE (IMG_H * IMG_W)
#define OPLANE (OUT_H * OUT_W)

#define TILE_OX 32
#define TILE_OY 16
#define NTX (OUT_W / TILE_OX)   // 10
#define NTY (OUT_H / TILE_OY)   // 3

#define SROWS 38
#define SCOLS 48                 // texel pitch; 384B/row; bank = x^swizzle mod 16
#define MAXF4 12                 // <= 12 float4-cells per row

#define NTHREADS 256

__device__ __forceinline__ uint32_t h2_to_u32(__half2 h) {
    uint32_t u;
    *reinterpret_cast<__half2*>(&u) = h;
    return u;
}
__device__ __forceinline__ __half2 u32_to_h2(uint32_t u) {
    return *reinterpret_cast<__half2*>(&u);
}

__global__ __launch_bounds__(NTHREADS, 8)
void rotated_roi_crop_v14(const float* __restrict__ x,
                          const float* __restrict__ boxes,
                          float* __restrict__ out) {
    __shared__ __align__(16) uint2 tileH[SROWS][SCOLS];
    __shared__ __align__(16) float fP[8];   // p1x,p1y,exx,exy | eyx,eyy,fx_al,fy_org
    __shared__ float fInv;
    __shared__ int   iP[4];                  // x_al, y_org, bhei, nf4row

    const int bid     = blockIdx.x;
    const int tx_tile = bid % NTX;
    const int ty_tile = (bid / NTX) % NTY;
    const int g       = bid / (NTX * NTY);
    const int tid     = threadIdx.x;

    // ---- thread-0 setup: box params + source window ----
    if (tid == 0) {
        const float* bp = boxes + g * 5;
        const float cx  = bp[0];
        const float cy  = bp[1];
        const float bw  = bp[2];
        const float bh  = bp[3];
        const float ang = bp[4];

        const float theta = -ang * 0.017453292519943295f;
        float s_, c_;
        sincosf(theta, &s_, &c_);
        const float b = c_ * 0.5f;
        const float a = s_ * 0.5f;

        const float p1x = cx + a * bh - b * bw;
        const float p1y = cy - b * bh - a * bw;
        const float eyx = -2.0f * a * bh;
        const float eyy =  2.0f * b * bh;
        const float exx = 2.0f * (cx - p1x) - eyx;
        const float exy = 2.0f * (cy - p1y) - eyy;

        const float u0 = (float)(tx_tile * TILE_OX)               * (1.0f / OUT_W);
        const float u1 = (float)(tx_tile * TILE_OX + TILE_OX - 1) * (1.0f / OUT_W);
        const float v0 = (float)(ty_tile * TILE_OY)               * (1.0f / OUT_H);
        const float v1 = (float)(ty_tile * TILE_OY + TILE_OY - 1) * (1.0f / OUT_H);

        const float sxa = p1x + u0 * exx + v0 * eyx;
        const float sxb = p1x + u1 * exx + v0 * eyx;
        const float sxc = p1x + u0 * exx + v1 * eyx;
        const float sxd = p1x + u1 * exx + v1 * eyx;
        const float sya = p1y + u0 * exy + v0 * eyy;
        const float syb = p1y + u1 * exy + v0 * eyy;
        const float syc = p1y + u0 * exy + v1 * eyy;
        const float syd = p1y + u1 * exy + v1 * eyy;

        const int fmin_x = (int)floorf(fminf(fminf(sxa, sxb), fminf(sxc, sxd)));
        const int fmax_x = (int)floorf(fmaxf(fmaxf(sxa, sxb), fmaxf(sxc, sxd)));
        const int fmin_y = (int)floorf(fminf(fminf(sya, syb), fminf(syc, syd)));
        const int fmax_y = (int)floorf(fmaxf(fmaxf(sya, syb), fmaxf(syc, syd)));

        const int x_org = fmin_x - 1;
        const int x_al  = x_org - (x_org & 3);
        const int y_org = fmin_y - 1;
        const int bhei  = min(fmax_y - fmin_y + 3, SROWS);
        const int nf4row = min((fmax_x + 2 - x_al + 4) >> 2, MAXF4);

        fP[0] = p1x;  fP[1] = p1y;  fP[2] = exx;  fP[3] = exy;
        fP[4] = eyx;  fP[5] = eyy;  fP[6] = (float)x_al;  fP[7] = (float)y_org;
        fInv  = 1.0f / (float)nf4row;
        iP[0] = x_al; iP[1] = y_org; iP[2] = bhei; iP[3] = nf4row;
    }
    __syncthreads();

    const int x_al   = iP[0];
    const int y_org  = iP[1];
    const int bhei   = iP[2];
    const int nf4row = iP[3];
    const float inv_nf4 = fInv;

    // ---- staging: bhei rows x nf4row float4-cells; fp16 pack; 2x STS.128 ----
    const int batch = g >> 6;
    const float* img = x + (size_t)batch * CHANS * PLANE;
    const int nf4 = nf4row * bhei;                  // <= 456

#pragma unroll
    for (int half_ = 0; half_ < 2; half_++) {
        const int i = tid + half_ * NTHREADS;
        if (i < nf4) {
            // exact for i<512, nf4row<=12
            const int yy  = (int)(((float)i + 0.5f) * inv_nf4);
            const int xx4 = i - yy * nf4row;
            const int gy  = y_org + yy;
            const int gxb = x_al + xx4 * 4;
            const bool ok = ((unsigned)gy < IMG_H) & ((unsigned)gxb <= (IMG_W - 4));
            float4 c0 = make_float4(0.f, 0.f, 0.f, 0.f);
            float4 c1 = c0, c2 = c0;
            if (ok) {
                const float* p = img + (size_t)gy * IMG_W + gxb;
                c0 = __ldg((const float4*)p);
                c1 = __ldg((const float4*)(p + PLANE));
                c2 = __ldg((const float4*)(p + 2 * PLANE));
            }
            uint4 w0, w1;
            w0.x = h2_to_u32(__floats2half2_rn(c0.x, c1.x));
            w0.y = h2_to_u32(__floats2half2_rn(c2.x, 0.f));
            w0.z = h2_to_u32(__floats2half2_rn(c0.y, c1.y));
            w0.w = h2_to_u32(__floats2half2_rn(c2.y, 0.f));
            w1.x = h2_to_u32(__floats2half2_rn(c0.z, c1.z));
            w1.y = h2_to_u32(__floats2half2_rn(c2.z, 0.f));
            w1.z = h2_to_u32(__floats2half2_rn(c0.w, c1.w));
            w1.w = h2_to_u32(__floats2half2_rn(c2.w, 0.f));
            // swizzled destination column (mask 4-aligned -> block contiguous)
            const int scol = (xx4 * 4) ^ ((yy & 3) << 2);
            uint4* d = (uint4*)&tileH[yy][scol];
            d[0] = w0;
            d[1] = w1;
        }
    }
    __syncthreads();

    // ---- compute: warp = 32 contiguous output px; 2 rows per thread ----
    const float4 fa = *(const float4*)&fP[0];   // p1x,p1y,exx,exy
    const float4 fb = *(const float4*)&fP[4];   // eyx,eyy,fx_al,fy_org

    const int lane = tid & 31;
    const int wrp  = tid >> 5;   // 0..7

    const int ox  = tx_tile * TILE_OX + lane;
    const int oy0 = ty_tile * TILE_OY + wrp * 2;

    const float u  = (float)ox  * (1.0f / OUT_W);
    const float vb = (float)oy0 * (1.0f / OUT_H);

    float sx = fmaf(vb, fb.x, fmaf(u, fa.z, fa.x)) - fb.z;
    float sy = fmaf(vb, fb.y, fmaf(u, fa.w, fa.y)) - fb.w;
    const float dvx = fb.x * (1.0f / OUT_H);
    const float dvy = fb.y * (1.0f / OUT_H);

    const uint2* __restrict__ tH = &tileH[0][0];

    float* ob = out + (((size_t)g * CHANS) * OUT_H + oy0) * OUT_W + ox;

#pragma unroll
    for (int r = 0; r < 2; r++) {
        const float x0f = floorf(sx);
        const float y0f = floorf(sy);
        const float dx = sx - x0f;
        const float dy = sy - y0f;

        int lx = min(max((int)x0f, 0), SCOLS - 4);   // safety; never binds in-spec
        int ly = min(max((int)y0f, 0), SROWS - 2);

        const int m0  = (ly & 3) << 2;
        const int m1  = ((ly + 1) & 3) << 2;
        const int rb0 = ly * SCOLS;
        const int rb1 = rb0 + SCOLS;
        const int i00 = rb0 + (lx ^ m0);
        const int i10 = rb0 + ((lx + 1) ^ m0);
        const int i01 = rb1 + (lx ^ m1);
        const int i11 = rb1 + ((lx + 1) ^ m1);

        const float omdx = 1.0f - dx;
        const float omdy = 1.0f - dy;
        const float w00 = omdx * omdy;
        const float w10 = dx * omdy;
        const float w01 = omdx * dy;
        const float w11 = dx * dy;

        const uint2 t00 = tH[i00];
        const uint2 t10 = tH[i10];
        const uint2 t01 = tH[i01];
        const uint2 t11 = tH[i11];

        const float2 ab00 = __half22float2(u32_to_h2(t00.x));
        const float2 ab10 = __half22float2(u32_to_h2(t10.x));
        const float2 ab01 = __half22float2(u32_to_h2(t01.x));
        const float2 ab11 = __half22float2(u32_to_h2(t11.x));
        const float  c00v = __low2float(u32_to_h2(t00.y));
        const float  c10v = __low2float(u32_to_h2(t10.y));
        const float  c01v = __low2float(u32_to_h2(t01.y));
        const float  c11v = __low2float(u32_to_h2(t11.y));

        const float r0 = fmaf(ab11.x, w11, fmaf(ab01.x, w01, fmaf(ab10.x, w10, ab00.x * w00)));
        const float r1 = fmaf(ab11.y, w11, fmaf(ab01.y, w01, fmaf(ab10.y, w10, ab00.y * w00)));
        const float r2 = fmaf(c11v,   w11, fmaf(c01v,   w01, fmaf(c10v,   w10, c00v   * w00)));

        ob[0]          = r0;
        ob[OPLANE]     = r1;
        ob[2 * OPLANE] = r2;

        sx += dvx;
        sy += dvy;
        ob += OUT_W;
    }
}

extern "C" void kernel_launch(void* const* d_in, const int* in_sizes, int n_in,
                              void* d_out, int out_size) {
    const float* x     = (const float*)d_in[0];
    const float* boxes = (const float*)d_in[1];
    float* out         = (float*)d_out;

    rotated_roi_crop_v14<<<N_BOXES_TOTAL * NTX * NTY, NTHREADS>>>(x, boxes, out);
}

// round 16
// speedup vs baseline: 1.0580x; 1.0580x over previous
#include <cuda_runtime.h>
#include <cuda_fp16.h>
#include <cstdint>

// Rotated ROI cropper v15: 32x32 output tiles (ragged 32x16 bottom band),
// fp16 texels, t0 setup broadcast. Fewer, fatter blocks: staged px per
// output px drops ~1.32 -> ~0.9 and per-block overhead amortizes 1.5x.
//   x:     [8, 3, 1024, 1024] fp32
//   boxes: [8, 64, 5] fp32  (cx, cy, w, h, angle_deg)
//   out:   [512, 3, 48, 320] fp32
//
// Window bound (bw<=300, bh<=60, |ang|<=45): 32x32 tile -> source span
// <= sqrt(29.06^2 + 38.75^2) = 48.4 px diag -> 52 rows x 56 cols incl.
// tap+guard+alignment. Staging: 3x LDG.128 per 4-texel cell -> fp16 texel
// (c0,c1,c2,0 in 8B) -> 2x STS.128. Tap = ONE LDS.64 for all 3 channels.

#define IMG_H 1024
#define IMG_W 1024
#define OUT_H 48
#define OUT_W 320
#define CHANS 3
#define N_BOXES_TOTAL 512
#define PLANE (IMG_H * IMG_W)
#define OPLANE (OUT_H * OUT_W)

#define TILE_OX 32
#define NTX (OUT_W / TILE_OX)   // 10
#define NBANDS 2                 // band0: rows 0..31 (TH=32); band1: rows 32..47 (TH=16)

#define SROWS 52
#define SCOLS 56                 // texel pitch (14 float4-cells); 448B/row
#define MAXF4 (SCOLS / 4)        // 14
#define IDX_LIM ((SROWS - 2) * SCOLS + (SCOLS - 2))

#define NTHREADS 256

__device__ __forceinline__ uint32_t h2_to_u32(__half2 h) {
    uint32_t u;
    *reinterpret_cast<__half2*>(&u) = h;
    return u;
}
__device__ __forceinline__ __half2 u32_to_h2(uint32_t u) {
    return *reinterpret_cast<__half2*>(&u);
}

__global__ __launch_bounds__(NTHREADS, 8)
void rotated_roi_crop_v15(const float* __restrict__ x,
                          const float* __restrict__ boxes,
                          float* __restrict__ out) {
    // Each texel: uint2 = { half2(c0,c1), half2(c2,0) } = 8 bytes.
    __shared__ __align__(16) uint2 tileH[SROWS][SCOLS];
    __shared__ __align__(16) float fP[8];   // p1x,p1y,exx,exy | eyx,eyy,fx_al,fy_org
    __shared__ float fInv;
    __shared__ int   iP[4];                  // x_al, y_org, bhei, nf4row

    const int bid     = blockIdx.x;
    const int tx_tile = bid % NTX;
    const int band    = (bid / NTX) % NBANDS;
    const int g       = bid / (NTX * NBANDS);
    const int tid     = threadIdx.x;

    const int oy_base = band * 32;
    const int TH      = band ? 16 : 32;      // tile height in output rows

    // ---- thread-0 setup: box params + source window ----
    if (tid == 0) {
        const float* bp = boxes + g * 5;
        const float cx  = bp[0];
        const float cy  = bp[1];
        const float bw  = bp[2];
        const float bh  = bp[3];
        const float ang = bp[4];

        const float theta = -ang * 0.017453292519943295f;
        float s_, c_;
        sincosf(theta, &s_, &c_);
        const float b = c_ * 0.5f;
        const float a = s_ * 0.5f;

        const float p1x = cx + a * bh - b * bw;
        const float p1y = cy - b * bh - a * bw;
        const float eyx = -2.0f * a * bh;
        const float eyy =  2.0f * b * bh;
        const float exx = 2.0f * (cx - p1x) - eyx;
        const float exy = 2.0f * (cy - p1y) - eyy;

        const float u0 = (float)(tx_tile * TILE_OX)               * (1.0f / OUT_W);
        const float u1 = (float)(tx_tile * TILE_OX + TILE_OX - 1) * (1.0f / OUT_W);
        const float v0 = (float)(oy_base)            * (1.0f / OUT_H);
        const float v1 = (float)(oy_base + TH - 1)   * (1.0f / OUT_H);

        const float sxa = p1x + u0 * exx + v0 * eyx;
        const float sxb = p1x + u1 * exx + v0 * eyx;
        const float sxc = p1x + u0 * exx + v1 * eyx;
        const float sxd = p1x + u1 * exx + v1 * eyx;
        const float sya = p1y + u0 * exy + v0 * eyy;
        const float syb = p1y + u1 * exy + v0 * eyy;
        const float syc = p1y + u0 * exy + v1 * eyy;
        const float syd = p1y + u1 * exy + v1 * eyy;

        const int fmin_x = (int)floorf(fminf(fminf(sxa, sxb), fminf(sxc, sxd)));
        const int fmax_x = (int)floorf(fmaxf(fmaxf(sxa, sxb), fmaxf(sxc, sxd)));
        const int fmin_y = (int)floorf(fminf(fminf(sya, syb), fminf(syc, syd)));
        const int fmax_y = (int)floorf(fmaxf(fmaxf(sya, syb), fmaxf(syc, syd)));

        const int x_org = fmin_x - 1;
        const int x_al  = x_org - (x_org & 3);
        const int y_org = fmin_y - 1;
        const int bhei  = min(fmax_y - fmin_y + 3, SROWS);
        const int nf4row = min((fmax_x + 2 - x_al + 4) >> 2, MAXF4);

        fP[0] = p1x;  fP[1] = p1y;  fP[2] = exx;  fP[3] = exy;
        fP[4] = eyx;  fP[5] = eyy;  fP[6] = (float)x_al;  fP[7] = (float)y_org;
        fInv  = 1.0f / (float)nf4row;
        iP[0] = x_al; iP[1] = y_org; iP[2] = bhei; iP[3] = nf4row;
    }
    __syncthreads();

    const int x_al   = iP[0];
    const int y_org  = iP[1];
    const int bhei   = iP[2];
    const int nf4row = iP[3];
    const float inv_nf4 = fInv;

    // ---- staging: bhei rows x nf4row float4-cells; fp16 pack; 2x STS.128 ----
    const int batch = g >> 6;
    const float* img = x + (size_t)batch * CHANS * PLANE;
    const int nf4 = nf4row * bhei;                  // <= 728

#pragma unroll
    for (int rnd = 0; rnd < 3; rnd++) {
        const int i = tid + rnd * NTHREADS;
        if (i < nf4) {
            // exact for i<2048, nf4row<=14
            const int yy  = (int)(((float)i + 0.5f) * inv_nf4);
            const int xx4 = i - yy * nf4row;
            const int gy  = y_org + yy;
            const int gxb = x_al + xx4 * 4;
            const bool ok = ((unsigned)gy < IMG_H) & ((unsigned)gxb <= (IMG_W - 4));
            float4 c0 = make_float4(0.f, 0.f, 0.f, 0.f);
            float4 c1 = c0, c2 = c0;
            if (ok) {
                const float* p = img + (size_t)gy * IMG_W + gxb;
                c0 = __ldg((const float4*)p);
                c1 = __ldg((const float4*)(p + PLANE));
                c2 = __ldg((const float4*)(p + 2 * PLANE));
            }
            uint4 w0, w1;
            w0.x = h2_to_u32(__floats2half2_rn(c0.x, c1.x));
            w0.y = h2_to_u32(__floats2half2_rn(c2.x, 0.f));
            w0.z = h2_to_u32(__floats2half2_rn(c0.y, c1.y));
            w0.w = h2_to_u32(__floats2half2_rn(c2.y, 0.f));
            w1.x = h2_to_u32(__floats2half2_rn(c0.z, c1.z));
            w1.y = h2_to_u32(__floats2half2_rn(c2.z, 0.f));
            w1.z = h2_to_u32(__floats2half2_rn(c0.w, c1.w));
            w1.w = h2_to_u32(__floats2half2_rn(c2.w, 0.f));
            uint4* d = (uint4*)&tileH[yy][xx4 * 4];
            d[0] = w0;
            d[1] = w1;
        }
    }
    __syncthreads();

    // ---- compute: warp = 32 contiguous output px; rows wrp, wrp+8, ... ----
    const float4 fa = *(const float4*)&fP[0];   // p1x,p1y,exx,exy
    const float4 fb = *(const float4*)&fP[4];   // eyx,eyy,fx_al,fy_org

    const int lane = tid & 31;
    const int wrp  = tid >> 5;   // 0..7

    const int ox  = tx_tile * TILE_OX + lane;
    const int oy0 = oy_base + wrp;               // rows stride 8 per r

    const float u  = (float)ox  * (1.0f / OUT_W);
    const float vb = (float)oy0 * (1.0f / OUT_H);

    float sx = fmaf(vb, fb.x, fmaf(u, fa.z, fa.x)) - fb.z;
    float sy = fmaf(vb, fb.y, fmaf(u, fa.w, fa.y)) - fb.w;
    const float dvx = fb.x * (8.0f / OUT_H);     // 8-row stride
    const float dvy = fb.y * (8.0f / OUT_H);

    const uint2* __restrict__ tH = &tileH[0][0];
    const int nrt = TH >> 3;                     // rows per thread: 4 or 2

    float* ob = out + (((size_t)g * CHANS) * OUT_H + oy0) * OUT_W + ox;

#pragma unroll
    for (int r = 0; r < 4; r++) {
        if (r < nrt) {
            const float x0f = floorf(sx);
            const float y0f = floorf(sy);
            const float dx = sx - x0f;
            const float dy = sy - y0f;

            int idx = (int)y0f * SCOLS + (int)x0f;
            idx = min(max(idx, 0), IDX_LIM);   // memory safety; never binds in-spec

            const float omdx = 1.0f - dx;
            const float omdy = 1.0f - dy;
            const float w00 = omdx * omdy;
            const float w10 = dx * omdy;
            const float w01 = omdx * dy;
            const float w11 = dx * dy;

            const uint2 t00 = tH[idx];
            const uint2 t10 = tH[idx + 1];
            const uint2 t01 = tH[idx + SCOLS];
            const uint2 t11 = tH[idx + SCOLS + 1];

            const float2 ab00 = __half22float2(u32_to_h2(t00.x));
            const float2 ab10 = __half22float2(u32_to_h2(t10.x));
            const float2 ab01 = __half22float2(u32_to_h2(t01.x));
            const float2 ab11 = __half22float2(u32_to_h2(t11.x));
            const float  c00v = __low2float(u32_to_h2(t00.y));
            const float  c10v = __low2float(u32_to_h2(t10.y));
            const float  c01v = __low2float(u32_to_h2(t01.y));
            const float  c11v = __low2float(u32_to_h2(t11.y));

            const float r0 = fmaf(ab11.x, w11, fmaf(ab01.x, w01, fmaf(ab10.x, w10, ab00.x * w00)));
            const float r1 = fmaf(ab11.y, w11, fmaf(ab01.y, w01, fmaf(ab10.y, w10, ab00.y * w00)));
            const float r2 = fmaf(c11v,   w11, fmaf(c01v,   w01, fmaf(c10v,   w10, c00v   * w00)));

            ob[0]          = r0;
            ob[OPLANE]     = r1;
            ob[2 * OPLANE] = r2;

            sx += dvx;
            sy += dvy;
            ob += 8 * OUT_W;
        }
    }
}

extern "C" void kernel_launch(void* const* d_in, const int* in_sizes, int n_in,
                              void* d_out, int out_size) {
    const float* x     = (const float*)d_in[0];
    const float* boxes = (const float*)d_in[1];
    float* out         = (float*)d_out;

    rotated_roi_crop_v15<<<N_BOXES_TOTAL * NTX * NBANDS, NTHREADS>>>(x, boxes, out);
}